// round 5
// baseline (speedup 1.0000x reference)
#include <cuda_runtime.h>
#include <math.h>

#define HD     128
#define HEADS  4
#define CDIM   32
#define NLAYER 4
#define NEG    100
#define HS     128

#define N_MAX  2048
#define E_MAX  4096
#define F_MAX  (N_MAX + E_MAX)

// ---------------- scratch (device globals; no allocation allowed) ----------
__device__ float g_h   [N_MAX * HD];
__device__ float g_e   [E_MAX * HD];
__device__ float g_xl  [N_MAX * HD];
__device__ float g_ssrc[N_MAX * HEADS];
__device__ float g_sdst[N_MAX * HEADS];
__device__ float g_ae  [E_MAX * HEADS];
__device__ float g_aesum[HEADS];
__device__ float g_alpha[F_MAX * HEADS];
__device__ float g_ex   [F_MAX * HEADS];
__device__ float g_m    [N_MAX * HEADS];
__device__ float g_den  [N_MAX * HEADS];
__device__ float g_agg  [N_MAX * HD];
__device__ float g_onsite[N_MAX];
__device__ float g_coup  [E_MAX];
__device__ int   g_dna  [N_MAX];
__device__ int   g_loc  [N_MAX];

// ---------------- small helpers -------------------------------------------
__device__ __forceinline__ void atomicMaxF(float* addr, float val) {
    int* ia = (int*)addr;
    int old = *ia;
    while (__int_as_float(old) < val) {
        int assumed = old;
        old = atomicCAS(ia, assumed, __float_as_int(val));
        if (old == assumed) break;
    }
}

__device__ __forceinline__ unsigned long long pk(float lo, float hi) {
    unsigned long long r;
    asm("mov.b64 %0, {%1, %2};" : "=l"(r) : "f"(lo), "f"(hi));
    return r;
}
__device__ __forceinline__ float2 upk(unsigned long long v) {
    float lo, hi;
    asm("mov.b64 {%0, %1}, %2;" : "=f"(lo), "=f"(hi) : "l"(v));
    return make_float2(lo, hi);
}
#define FFMA2(d, a, b, c) \
    asm("fma.rn.f32x2 %0, %1, %2, %3;" : "=l"(d) : "l"(a), "l"(b), "l"(c))

// ---------------- GNN kernels ----------------------------------------------
__global__ void k_init_h(const float* __restrict__ x, const float* __restrict__ w,
                         const float* __restrict__ b) {
    int n = blockIdx.x, t = threadIdx.x;
    float acc = b[t];
#pragma unroll
    for (int k = 0; k < 4; k++) acc = fmaf(x[n * 4 + k], w[k * HD + t], acc);
    g_h[n * HD + t] = acc;
    g_agg[n * HD + t] = 0.f;
    if (t < HEADS) { g_m[n * HEADS + t] = -3.0e38f; g_den[n * HEADS + t] = 0.f; }
    if (n == 0 && t < HEADS) g_aesum[t] = 0.f;
}

__global__ void k_init_e(const float* __restrict__ ea, const float* __restrict__ w,
                         const float* __restrict__ b) {
    int n = blockIdx.x, t = threadIdx.x;
    float acc = b[t];
#pragma unroll
    for (int k = 0; k < 5; k++) acc = fmaf(ea[n * 5 + k], w[k * HD + t], acc);
    g_e[n * HD + t] = acc;
}

// fused xl (nodes) + edge-attention projection: 4 rows per block
__global__ void k_attn(const float* __restrict__ Wn, const float* __restrict__ asrc,
                       const float* __restrict__ adst, const float* __restrict__ We,
                       const float* __restrict__ aedge, int N, int E, int nb_n) {
    __shared__ float rows[4][HD];
    __shared__ float outs[4][HD];
    int t = threadIdx.x;
    bool isnode = (blockIdx.x < nb_n);
    int r0 = (isnode ? blockIdx.x : blockIdx.x - nb_n) * 4;
    int cnt = (isnode ? N : E) - r0; if (cnt > 4) cnt = 4;
    const float* base = isnode ? g_h : g_e;
    const float* W = isnode ? Wn : We;
#pragma unroll
    for (int rr = 0; rr < 4; rr++)
        rows[rr][t] = (rr < cnt) ? base[(r0 + rr) * HD + t] : 0.f;
    __syncthreads();
    float a0 = 0.f, a1 = 0.f, a2 = 0.f, a3 = 0.f;
#pragma unroll 4
    for (int k = 0; k < HD; k++) {
        float wv = W[k * HD + t];
        a0 = fmaf(rows[0][k], wv, a0);
        a1 = fmaf(rows[1][k], wv, a1);
        a2 = fmaf(rows[2][k], wv, a2);
        a3 = fmaf(rows[3][k], wv, a3);
    }
    outs[0][t] = a0; outs[1][t] = a1; outs[2][t] = a2; outs[3][t] = a3;
    if (isnode) {
        if (0 < cnt) g_xl[(r0 + 0) * HD + t] = a0;
        if (1 < cnt) g_xl[(r0 + 1) * HD + t] = a1;
        if (2 < cnt) g_xl[(r0 + 2) * HD + t] = a2;
        if (3 < cnt) g_xl[(r0 + 3) * HD + t] = a3;
    }
    __syncthreads();
    int w = t >> 5, lane = t & 31;
    if (w < cnt) {
        if (isnode) {
#pragma unroll
            for (int h = 0; h < HEADS; h++) {
                float x = outs[w][h * 32 + lane];
                float vs = x * asrc[h * 32 + lane];
                float vd = x * adst[h * 32 + lane];
#pragma unroll
                for (int o = 16; o > 0; o >>= 1) {
                    vs += __shfl_down_sync(0xffffffffu, vs, o);
                    vd += __shfl_down_sync(0xffffffffu, vd, o);
                }
                if (lane == 0) {
                    g_ssrc[(r0 + w) * HEADS + h] = vs;
                    g_sdst[(r0 + w) * HEADS + h] = vd;
                }
            }
        } else {
#pragma unroll
            for (int h = 0; h < HEADS; h++) {
                float v = outs[w][h * 32 + lane] * aedge[h * 32 + lane];
#pragma unroll
                for (int o = 16; o > 0; o >>= 1) v += __shfl_down_sync(0xffffffffu, v, o);
                if (lane == 0) {
                    g_ae[(r0 + w) * HEADS + h] = v;
                    atomicAdd(&g_aesum[h], v);
                }
            }
        }
    }
}

__global__ void k_alpha(const int* __restrict__ src, const int* __restrict__ dst,
                        int N, int E) {
    int idx = blockIdx.x * blockDim.x + threadIdx.x;
    int F = E + N;
    if (idx >= F * HEADS) return;
    int f = idx >> 2, hh = idx & 3;
    int s, d; float ae;
    if (f < E) { s = src[f]; d = dst[f]; ae = g_ae[f * HEADS + hh]; }
    else       { s = f - E; d = s;       ae = g_aesum[hh] / (float)E; }
    float a = g_ssrc[s * HEADS + hh] + g_sdst[d * HEADS + hh] + ae;
    a = a > 0.f ? a : 0.2f * a;
    g_alpha[idx] = a;
    atomicMaxF(&g_m[d * HEADS + hh], a);
}

__global__ void k_ex(const int* __restrict__ dst, int N, int E) {
    int idx = blockIdx.x * blockDim.x + threadIdx.x;
    int F = E + N;
    if (idx >= F * HEADS) return;
    int f = idx >> 2, hh = idx & 3;
    int d = (f < E) ? dst[f] : (f - E);
    float ex = expf(g_alpha[idx] - g_m[d * HEADS + hh]);
    g_ex[idx] = ex;
    atomicAdd(&g_den[d * HEADS + hh], ex);
}

__global__ void k_agg(const int* __restrict__ src, const int* __restrict__ dst,
                      int N, int E) {
    int f = blockIdx.x, t = threadIdx.x;
    int s, d;
    if (f < E) { s = src[f]; d = dst[f]; }
    else       { s = f - E;  d = s; }
    int hh = t >> 5;
    float w = g_ex[f * HEADS + hh] / g_den[d * HEADS + hh];
    atomicAdd(&g_agg[d * HD + t], g_xl[s * HD + t] * w);
}

// layernorm(relu(agg+bias) + h) and zero the accumulators for the next layer
__global__ void k_ln(const float* __restrict__ bias, const float* __restrict__ s,
                     const float* __restrict__ bb) {
    __shared__ float red[HD];
    int n = blockIdx.x, t = threadIdx.x;
    float v = g_agg[n * HD + t] + bias[t];
    g_agg[n * HD + t] = 0.f;
    v = v > 0.f ? v : 0.f;
    v += g_h[n * HD + t];
    red[t] = v; __syncthreads();
#pragma unroll
    for (int o = 64; o > 0; o >>= 1) { if (t < o) red[t] += red[t + o]; __syncthreads(); }
    float mu = red[0] / (float)HD;
    __syncthreads();
    float dd = v - mu;
    red[t] = dd * dd; __syncthreads();
#pragma unroll
    for (int o = 64; o > 0; o >>= 1) { if (t < o) red[t] += red[t + o]; __syncthreads(); }
    float var = red[0] / (float)HD;
    g_h[n * HD + t] = dd * rsqrtf(var + 1e-5f) * s[t] + bb[t];
    if (t < HEADS) { g_m[n * HEADS + t] = -3.0e38f; g_den[n * HEADS + t] = 0.f; }
    if (n == 0 && t < HEADS) g_aesum[t] = 0.f;
}

// onsite (nodes) + coupling (edges) MLPs: 128 -> 64 (relu) -> 1
__global__ void k_mlp(const float* __restrict__ w1, const float* __restrict__ b1,
                      const float* __restrict__ w2, const float* __restrict__ b2,
                      const float* __restrict__ cw1, const float* __restrict__ cb1,
                      const float* __restrict__ cw2, const float* __restrict__ cb2,
                      int N) {
    __shared__ float in[HD];
    __shared__ float red[64];
    int blk = blockIdx.x, t = threadIdx.x;
    const float *row, *W1, *B1, *W2, *B2;
    if (blk < N) { row = &g_h[blk * HD];        W1 = w1;  B1 = b1;  W2 = w2;  B2 = b2;  }
    else         { row = &g_e[(blk - N) * HD];  W1 = cw1; B1 = cb1; W2 = cw2; B2 = cb2; }
    in[t] = row[t]; in[t + 64] = row[t + 64];
    __syncthreads();
    float acc = B1[t];
#pragma unroll 8
    for (int k = 0; k < HD; k++) acc = fmaf(in[k], W1[k * 64 + t], acc);
    acc = acc > 0.f ? acc : 0.f;
    red[t] = acc * W2[t];
    __syncthreads();
#pragma unroll
    for (int o = 32; o > 0; o >>= 1) { if (t < o) red[t] += red[t + o]; __syncthreads(); }
    if (t == 0) {
        float o = red[0] + B2[0];
        if (blk < N) g_onsite[blk] = o; else g_coup[blk - N] = o;
    }
}

// dna mask + local dna-index per graph (serial scan over <=2048 nodes in smem)
__global__ void k_dna(const float* __restrict__ x, const int* __restrict__ batch, int N) {
    __shared__ int mi[N_MAX];
    __shared__ int bt[N_MAX];
    __shared__ int lo[N_MAX];
    int t = threadIdx.x;
    for (int n = t; n < N; n += blockDim.x) {
        float a = x[n * 4], b = x[n * 4 + 1], c = x[n * 4 + 2], d = x[n * 4 + 3];
        int dna = (a != 0.f || b != 0.f || c != 0.f || d != 0.f) ? 1 : 0;
        mi[n] = dna;
        g_dna[n] = dna;
        bt[n] = batch[n];
    }
    __syncthreads();
    if (t == 0) {
        int cum = 0, curb = -1, gstart = 0;
        for (int n = 0; n < N; n++) {
            int b = bt[n];
            if (b != curb) { curb = b; gstart = cum; }
            lo[n] = cum - gstart;
            cum += mi[n];
        }
    }
    __syncthreads();
    for (int n = t; n < N; n += blockDim.x) g_loc[n] = lo[n];
}

__global__ void k_hinit(float* __restrict__ H, int B) {
    int idx = blockIdx.x * blockDim.x + threadIdx.x;
    if (idx >= B * HS * HS) return;
    int r = (idx % (HS * HS)) / HS, c = idx % HS;
    H[idx] = (r == c) ? 1e-6f : 0.f;
}

__global__ void k_hdiag(const int* __restrict__ batch, float* __restrict__ H, int N) {
    int n = blockIdx.x * blockDim.x + threadIdx.x;
    if (n >= N) return;
    if (g_dna[n]) {
        int b = batch[n], l = g_loc[n];
        H[b * HS * HS + l * HS + l] += g_onsite[n];
    }
}

__global__ void k_hedge(const int* __restrict__ src, const int* __restrict__ dst,
                        const int* __restrict__ batch, float* __restrict__ H, int E) {
    int e = blockIdx.x * blockDim.x + threadIdx.x;
    if (e >= E) return;
    int s = src[e], d = dst[e];
    if (g_dna[s] && g_dna[d]) {
        int b = batch[s], u = g_loc[s], v = g_loc[d];
        float cv = g_coup[e];
        atomicAdd(&H[b * HS * HS + u * HS + v], cv);
        atomicAdd(&H[b * HS * HS + v * HS + u], cv);
    }
}

// ---------------- NEGF: one CTA per (graph, energy) ------------------------
// Gr = inv(A + i*D). Rank-8 blocked, unpivoted complex Gauss-Jordan.
// W in registers (packed f32x2 in b64). Updates use fma.rn.f32x2.
#define NB    8
#define NBLK  (HS / NB)
#define NTHR  512

// complex fma: m -= c * r (scalar form, for panel math)
#define CFMS(m, c, r) do { \
    m.x = fmaf(-(c).x, (r).x, fmaf((c).y, (r).y, m.x)); \
    m.y = fmaf(-(c).x, (r).y, fmaf(-(c).y, (r).x, m.y)); \
} while (0)
#define CMUL(o, a, b) do { \
    o.x = (a).x * (b).x - (a).y * (b).y; \
    o.y = (a).x * (b).y + (a).y * (b).x; \
} while (0)

__global__ void __launch_bounds__(NTHR, 1) k_negf(
    const float* __restrict__ GL, const float* __restrict__ GR,
    const float* __restrict__ Hin, float* __restrict__ Tout,
    float* __restrict__ Dout) {
    __shared__ ulonglong2 Cs2[HS][NB];   // {(-cx,-cx),(cy,cy)} per (row, q)  16KB
    __shared__ ulonglong2 Rs [NB][64];   // {(r0x,r0y),(r1x,r1y)}            8KB
    __shared__ ulonglong2 Rsn[NB][64];   // {(r0y,-r0x),(r1y,-r1x)}          8KB
    __shared__ float2 Ws[NB][HS];        // old K-rows staging                8KB
    __shared__ float2 Pb[NB][NB];
    __shared__ float  glv[HS], grv[HS];
    __shared__ float  rsum[16], rtr[16];

    int tid  = threadIdx.x;
    int fc   = tid & 63;                 // owns complex cols 2fc, 2fc+1
    int rq   = tid >> 6;                 // owns rows rq*16 .. rq*16+15
    int warp = tid >> 5, lane = tid & 31;
    int b = blockIdx.x / NEG, ei = blockIdx.x % NEG;
    float Eg = (float)(-3.0 + 6.0 * (double)ei / 99.0);
    const float2* Hb2 = (const float2*)(Hin + (size_t)b * HS * HS);

    if (tid < HS) {
        glv[tid] = GL[b * HS + tid];
        grv[tid] = GR[b * HS + tid];
    }
    __syncthreads();

    // W = A + i*D packed: w[ii][c] = (re, im) of elem (rq*16+ii, 2fc+c)
    unsigned long long w[16][2];
#pragma unroll
    for (int ii = 0; ii < 16; ii++) {
        int i = rq * 16 + ii;
        float2 hv = Hb2[i * 64 + fc];
        float dvi = 0.5f * (glv[i] + grv[i]) + 1e-12f;
        int j0 = 2 * fc;
        w[ii][0] = pk(((i == j0)     ? Eg : 0.f) - hv.x, (i == j0)     ? dvi : 0.f);
        w[ii][1] = pk(((i == j0 + 1) ? Eg : 0.f) - hv.y, (i == j0 + 1) ? dvi : 0.f);
    }

    for (int kb = 0; kb < NBLK; kb++) {
        int c0 = kb * NB;
        bool blockcol = ((fc >> 2) == kb);
        bool krows = (rq == (kb >> 1));
        int base = (kb & 1) * 8;

        // ---- phase 1: column panel (packed) + K-row staging ---------------
        if (blockcol) {
            int q0 = (fc & 3) * 2;
#pragma unroll
            for (int ii = 0; ii < 16; ii++) {
                int i = rq * 16 + ii;
                float2 cA = upk(w[ii][0]), cB = upk(w[ii][1]);
                Cs2[i][q0]     = make_ulonglong2(pk(-cA.x, -cA.x), pk(cA.y, cA.y));
                Cs2[i][q0 + 1] = make_ulonglong2(pk(-cB.x, -cB.x), pk(cB.y, cB.y));
            }
        }
        if (krows) {
#pragma unroll
            for (int p = 0; p < NB; p++) {
                Ws[p][2 * fc]     = upk(w[base + p][0]);
                Ws[p][2 * fc + 1] = upk(w[base + p][1]);
            }
        }
        __syncthreads();

        // ---- phase 2: Pinv (8x8) by warp 0 --------------------------------
        if (warp == 0) {
#pragma unroll
            for (int e2 = 0; e2 < 2; e2++) {
                int e = lane + e2 * 32;
                Pb[e >> 3][e & 7] = Ws[e >> 3][c0 + (e & 7)];
            }
            __syncwarp();
            for (int kk = 0; kk < NB; kk++) {
                float2 pv = Pb[kk][kk];
                float inv = 1.f / fmaf(pv.x, pv.x, pv.y * pv.y);
                float2 ip = make_float2(pv.x * inv, -pv.y * inv);
                float2 nv[2];
#pragma unroll
                for (int e2 = 0; e2 < 2; e2++) {
                    int e = lane + e2 * 32, r = e >> 3, c = e & 7;
                    float2 old  = Pb[r][c];
                    float2 rowk = Pb[kk][c];
                    float2 colk = Pb[r][kk];
                    if (r == kk && c == kk) nv[e2] = ip;
                    else if (r == kk)       { CMUL(nv[e2], rowk, ip); }
                    else if (c == kk) {
                        float2 t; CMUL(t, colk, ip);
                        nv[e2] = make_float2(-t.x, -t.y);
                    } else {
                        float2 kr; CMUL(kr, rowk, ip);
                        nv[e2] = old; CFMS(nv[e2], colk, kr);
                    }
                }
                __syncwarp();
#pragma unroll
                for (int e2 = 0; e2 < 2; e2++) {
                    int e = lane + e2 * 32;
                    Pb[e >> 3][e & 7] = nv[e2];
                }
                __syncwarp();
            }
        }
        __syncthreads();

        // ---- phase 3: row panel R = Pinv * Wold[K,:], all threads (q = rq)
        {
            int q = rq;
            float2 a0, a1;
            if (blockcol) {
                int jj = (fc & 3) * 2;
                a0 = Pb[q][jj]; a1 = Pb[q][jj + 1];
            } else {
                a0 = make_float2(0.f, 0.f); a1 = make_float2(0.f, 0.f);
#pragma unroll
                for (int p = 0; p < NB; p++) {
                    float2 pi = Pb[q][p];
                    float2 u0 = Ws[p][2 * fc], u1 = Ws[p][2 * fc + 1];
                    a0.x = fmaf(pi.x, u0.x, fmaf(-pi.y, u0.y, a0.x));
                    a0.y = fmaf(pi.x, u0.y, fmaf( pi.y, u0.x, a0.y));
                    a1.x = fmaf(pi.x, u1.x, fmaf(-pi.y, u1.y, a1.x));
                    a1.y = fmaf(pi.x, u1.y, fmaf( pi.y, u1.x, a1.y));
                }
            }
            Rs [q][fc] = make_ulonglong2(pk(a0.x, a0.y),  pk(a1.x, a1.y));
            Rsn[q][fc] = make_ulonglong2(pk(a0.y, -a0.x), pk(a1.y, -a1.x));
        }
        __syncthreads();

        // ---- phase 4: rank-8 update on packed register tile ---------------
        if (blockcol) {
#pragma unroll
            for (int ii = 0; ii < 16; ii++) { w[ii][0] = 0ull; w[ii][1] = 0ull; }
        }
#pragma unroll 2
        for (int q = 0; q < NB; q++) {
            ulonglong2 rr = Rs[q][fc];
            ulonglong2 rn = Rsn[q][fc];
#pragma unroll
            for (int ii = 0; ii < 16; ii++) {
                ulonglong2 uv = Cs2[rq * 16 + ii][q];
                FFMA2(w[ii][0], uv.x, rr.x, w[ii][0]);
                FFMA2(w[ii][0], uv.y, rn.x, w[ii][0]);
                FFMA2(w[ii][1], uv.x, rr.y, w[ii][1]);
                FFMA2(w[ii][1], uv.y, rn.y, w[ii][1]);
            }
        }
        if (krows) {
#pragma unroll
            for (int q = 0; q < NB; q++) {
                ulonglong2 rr = Rs[q][fc];
                w[base + q][0] = rr.x;
                w[base + q][1] = rr.y;
            }
        }
        __syncthreads();
    }

    // ---- outputs: T = sum_ij GL_i |G_ij|^2 GR_j ; dos = -tr(Im G)/pi ------
    float tpart = 0.f, dpart = 0.f;
    int j0 = 2 * fc;
    float gr0 = grv[j0], gr1 = grv[j0 + 1];
#pragma unroll
    for (int ii = 0; ii < 16; ii++) {
        int i = rq * 16 + ii;
        float2 g0 = upk(w[ii][0]), g1 = upk(w[ii][1]);
        tpart += glv[i] * (gr0 * fmaf(g0.x, g0.x, g0.y * g0.y) +
                           gr1 * fmaf(g1.x, g1.x, g1.y * g1.y));
        if (i == j0)     dpart += g0.y;
        if (i == j0 + 1) dpart += g1.y;
    }
#pragma unroll
    for (int o = 16; o > 0; o >>= 1) {
        tpart += __shfl_down_sync(0xffffffffu, tpart, o);
        dpart += __shfl_down_sync(0xffffffffu, dpart, o);
    }
    if (lane == 0) { rsum[warp] = tpart; rtr[warp] = dpart; }
    __syncthreads();
    if (tid == 0) {
        float ts = 0.f, tr = 0.f;
#pragma unroll
        for (int ww = 0; ww < 16; ww++) { ts += rsum[ww]; tr += rtr[ww]; }
        Tout[b * NEG + ei] = log10f(fmaxf(ts, 1e-16f));
        Dout[b * NEG + ei] = log10f(fmaxf(-tr / 3.14159265358979323846f, 1e-16f));
    }
}

// ---------------- launch ----------------------------------------------------
extern "C" void kernel_launch(void* const* d_in, const int* in_sizes, int n_in,
                              void* d_out, int out_size) {
    const float* x      = (const float*)d_in[0];
    const int*   ei     = (const int*)  d_in[1];
    const float* ea     = (const float*)d_in[2];
    const int*   batch  = (const int*)  d_in[3];
    const float* GL     = (const float*)d_in[4];
    const float* GR     = (const float*)d_in[5];
    const float* node_w = (const float*)d_in[6];
    const float* node_b = (const float*)d_in[7];
    const float* edgep_w= (const float*)d_in[8];
    const float* edgep_b= (const float*)d_in[9];
    const float* gat_lin= (const float*)d_in[10];
    const float* att_src= (const float*)d_in[11];
    const float* att_dst= (const float*)d_in[12];
    const float* gat_le = (const float*)d_in[13];
    const float* att_ed = (const float*)d_in[14];
    const float* gat_b  = (const float*)d_in[15];
    const float* ln_s   = (const float*)d_in[16];
    const float* ln_b   = (const float*)d_in[17];
    const float* on_w1  = (const float*)d_in[18];
    const float* on_b1  = (const float*)d_in[19];
    const float* on_w2  = (const float*)d_in[20];
    const float* on_b2  = (const float*)d_in[21];
    const float* cp_w1  = (const float*)d_in[22];
    const float* cp_b1  = (const float*)d_in[23];
    const float* cp_w2  = (const float*)d_in[24];
    const float* cp_b2  = (const float*)d_in[25];

    int N = in_sizes[0] / 4;
    int E = in_sizes[2] / 5;
    int B = in_sizes[4] / HS;
    const int* src = ei;
    const int* dst = ei + E;

    float* out  = (float*)d_out;
    float* Tout = out;
    float* Dout = out + B * NEG;
    float* Hout = out + 2 * B * NEG;

    k_init_h<<<N, HD>>>(x, node_w, node_b);
    k_init_e<<<E, HD>>>(ea, edgep_w, edgep_b);

    int F = (E + N) * HEADS;
    int nb_n = (N + 3) / 4, nb_e = (E + 3) / 4;
    for (int l = 0; l < NLAYER; l++) {
        k_attn <<<nb_n + nb_e, HD>>>(gat_lin + l * HD * HD, att_src + l * HEADS * CDIM,
                                     att_dst + l * HEADS * CDIM, gat_le + l * HD * HD,
                                     att_ed + l * HEADS * CDIM, N, E, nb_n);
        k_alpha<<<(F + 255) / 256, 256>>>(src, dst, N, E);
        k_ex   <<<(F + 255) / 256, 256>>>(dst, N, E);
        k_agg  <<<E + N, HD>>>(src, dst, N, E);
        k_ln   <<<N, HD>>>(gat_b + l * HD, ln_s + l * HD, ln_b + l * HD);
    }

    k_mlp  <<<N + E, 64>>>(on_w1, on_b1, on_w2, on_b2, cp_w1, cp_b1, cp_w2, cp_b2, N);
    k_dna  <<<1, 1024>>>(x, batch, N);
    k_hinit<<<(B * HS * HS + 255) / 256, 256>>>(Hout, B);
    k_hdiag<<<(N + 255) / 256, 256>>>(batch, Hout, N);
    k_hedge<<<(E + 255) / 256, 256>>>(src, dst, batch, Hout, E);

    k_negf<<<B * NEG, NTHR>>>(GL, GR, Hout, Tout, Dout);
}

// round 6
// speedup vs baseline: 1.2557x; 1.2557x over previous
#include <cuda_runtime.h>
#include <math.h>

#define HD     128
#define HEADS  4
#define CDIM   32
#define NLAYER 4
#define NEG    100
#define HS     128

#define N_MAX  2048
#define E_MAX  4096
#define F_MAX  (N_MAX + E_MAX)

// ---------------- scratch (device globals; no allocation allowed) ----------
__device__ float g_h   [N_MAX * HD];
__device__ float g_e   [E_MAX * HD];
__device__ float g_xl  [N_MAX * HD];
__device__ float g_ssrc[N_MAX * HEADS];
__device__ float g_sdst[N_MAX * HEADS];
__device__ float g_ae  [E_MAX * HEADS];
__device__ float g_aesum[HEADS];
__device__ float g_alpha[F_MAX * HEADS];
__device__ float g_ex   [F_MAX * HEADS];
__device__ float g_den  [N_MAX * HEADS];
__device__ float g_agg  [N_MAX * HD];
__device__ float g_onsite[N_MAX];
__device__ float g_coup  [E_MAX];
__device__ int   g_dna  [N_MAX];
__device__ int   g_loc  [N_MAX];

// ---------------- small helpers -------------------------------------------
__device__ __forceinline__ void atomicMaxFS(float* addr, float val) {
    int* ia = (int*)addr;
    int old = *ia;
    while (__int_as_float(old) < val) {
        int assumed = old;
        old = atomicCAS(ia, assumed, __float_as_int(val));
        if (old == assumed) break;
    }
}

// ---------------- GNN kernels ----------------------------------------------
__global__ void k_init_h(const float* __restrict__ x, const float* __restrict__ w,
                         const float* __restrict__ b) {
    int n = blockIdx.x, t = threadIdx.x;
    float acc = b[t];
#pragma unroll
    for (int k = 0; k < 4; k++) acc = fmaf(x[n * 4 + k], w[k * HD + t], acc);
    g_h[n * HD + t] = acc;
    g_agg[n * HD + t] = 0.f;
    if (n == 0 && t < HEADS) g_aesum[t] = 0.f;
}

__global__ void k_init_e(const float* __restrict__ ea, const float* __restrict__ w,
                         const float* __restrict__ b) {
    int n = blockIdx.x, t = threadIdx.x;
    float acc = b[t];
#pragma unroll
    for (int k = 0; k < 5; k++) acc = fmaf(ea[n * 5 + k], w[k * HD + t], acc);
    g_e[n * HD + t] = acc;
}

// fused xl (nodes) + edge-attention projection: 4 rows per block
__global__ void k_attn(const float* __restrict__ Wn, const float* __restrict__ asrc,
                       const float* __restrict__ adst, const float* __restrict__ We,
                       const float* __restrict__ aedge, int N, int E, int nb_n) {
    __shared__ float rows[4][HD];
    __shared__ float outs[4][HD];
    int t = threadIdx.x;
    bool isnode = (blockIdx.x < nb_n);
    int r0 = (isnode ? blockIdx.x : blockIdx.x - nb_n) * 4;
    int cnt = (isnode ? N : E) - r0; if (cnt > 4) cnt = 4;
    const float* base = isnode ? g_h : g_e;
    const float* W = isnode ? Wn : We;
#pragma unroll
    for (int rr = 0; rr < 4; rr++)
        rows[rr][t] = (rr < cnt) ? base[(r0 + rr) * HD + t] : 0.f;
    __syncthreads();
    float a0 = 0.f, a1 = 0.f, a2 = 0.f, a3 = 0.f;
#pragma unroll 4
    for (int k = 0; k < HD; k++) {
        float wv = W[k * HD + t];
        a0 = fmaf(rows[0][k], wv, a0);
        a1 = fmaf(rows[1][k], wv, a1);
        a2 = fmaf(rows[2][k], wv, a2);
        a3 = fmaf(rows[3][k], wv, a3);
    }
    outs[0][t] = a0; outs[1][t] = a1; outs[2][t] = a2; outs[3][t] = a3;
    if (isnode) {
        if (0 < cnt) g_xl[(r0 + 0) * HD + t] = a0;
        if (1 < cnt) g_xl[(r0 + 1) * HD + t] = a1;
        if (2 < cnt) g_xl[(r0 + 2) * HD + t] = a2;
        if (3 < cnt) g_xl[(r0 + 3) * HD + t] = a3;
    }
    __syncthreads();
    int w = t >> 5, lane = t & 31;
    if (w < cnt) {
        if (isnode) {
#pragma unroll
            for (int h = 0; h < HEADS; h++) {
                float x = outs[w][h * 32 + lane];
                float vs = x * asrc[h * 32 + lane];
                float vd = x * adst[h * 32 + lane];
#pragma unroll
                for (int o = 16; o > 0; o >>= 1) {
                    vs += __shfl_down_sync(0xffffffffu, vs, o);
                    vd += __shfl_down_sync(0xffffffffu, vd, o);
                }
                if (lane == 0) {
                    g_ssrc[(r0 + w) * HEADS + h] = vs;
                    g_sdst[(r0 + w) * HEADS + h] = vd;
                }
            }
        } else {
#pragma unroll
            for (int h = 0; h < HEADS; h++) {
                float v = outs[w][h * 32 + lane] * aedge[h * 32 + lane];
#pragma unroll
                for (int o = 16; o > 0; o >>= 1) v += __shfl_down_sync(0xffffffffu, v, o);
                if (lane == 0) {
                    g_ae[(r0 + w) * HEADS + h] = v;
                    atomicAdd(&g_aesum[h], v);
                }
            }
        }
    }
}

// fused alpha + segment-max + exp + segment-sum: single CTA, smem accumulators
__global__ void k_softmax(const int* __restrict__ src, const int* __restrict__ dst,
                          int N, int E) {
    extern __shared__ float sm[];
    float* m_s = sm;
    float* d_s = sm + N * HEADS;
    int t = threadIdx.x, NT = blockDim.x;
    int NH = N * HEADS, F = E + N;
    for (int i = t; i < NH; i += NT) { m_s[i] = -3.0e38f; d_s[i] = 0.f; }
    __syncthreads();
    for (int idx = t; idx < F * HEADS; idx += NT) {
        int f = idx >> 2, hh = idx & 3;
        int s, d; float ae;
        if (f < E) { s = src[f]; d = dst[f]; ae = g_ae[f * HEADS + hh]; }
        else       { s = f - E; d = s;       ae = g_aesum[hh] / (float)E; }
        float a = g_ssrc[s * HEADS + hh] + g_sdst[d * HEADS + hh] + ae;
        a = a > 0.f ? a : 0.2f * a;
        g_alpha[idx] = a;
        atomicMaxFS(&m_s[d * HEADS + hh], a);
    }
    __syncthreads();
    for (int idx = t; idx < F * HEADS; idx += NT) {
        int f = idx >> 2, hh = idx & 3;
        int d = (f < E) ? dst[f] : (f - E);
        float ex = expf(g_alpha[idx] - m_s[d * HEADS + hh]);
        g_ex[idx] = ex;
        atomicAdd(&d_s[d * HEADS + hh], ex);
    }
    __syncthreads();
    for (int i = t; i < NH; i += NT) g_den[i] = d_s[i];
}

__global__ void k_agg(const int* __restrict__ src, const int* __restrict__ dst,
                      int N, int E) {
    int f = blockIdx.x, t = threadIdx.x;
    int s, d;
    if (f < E) { s = src[f]; d = dst[f]; }
    else       { s = f - E;  d = s; }
    int hh = t >> 5;
    float w = g_ex[f * HEADS + hh] / g_den[d * HEADS + hh];
    atomicAdd(&g_agg[d * HD + t], g_xl[s * HD + t] * w);
}

// layernorm(relu(agg+bias) + h) and zero accumulators for the next layer
__global__ void k_ln(const float* __restrict__ bias, const float* __restrict__ s,
                     const float* __restrict__ bb) {
    __shared__ float red[HD];
    int n = blockIdx.x, t = threadIdx.x;
    float v = g_agg[n * HD + t] + bias[t];
    g_agg[n * HD + t] = 0.f;
    v = v > 0.f ? v : 0.f;
    v += g_h[n * HD + t];
    red[t] = v; __syncthreads();
#pragma unroll
    for (int o = 64; o > 0; o >>= 1) { if (t < o) red[t] += red[t + o]; __syncthreads(); }
    float mu = red[0] / (float)HD;
    __syncthreads();
    float dd = v - mu;
    red[t] = dd * dd; __syncthreads();
#pragma unroll
    for (int o = 64; o > 0; o >>= 1) { if (t < o) red[t] += red[t + o]; __syncthreads(); }
    float var = red[0] / (float)HD;
    g_h[n * HD + t] = dd * rsqrtf(var + 1e-5f) * s[t] + bb[t];
    if (n == 0 && t < HEADS) g_aesum[t] = 0.f;
}

// onsite (nodes) + coupling (edges) MLPs: 128 -> 64 (relu) -> 1
__global__ void k_mlp(const float* __restrict__ w1, const float* __restrict__ b1,
                      const float* __restrict__ w2, const float* __restrict__ b2,
                      const float* __restrict__ cw1, const float* __restrict__ cb1,
                      const float* __restrict__ cw2, const float* __restrict__ cb2,
                      int N) {
    __shared__ float in[HD];
    __shared__ float red[64];
    int blk = blockIdx.x, t = threadIdx.x;
    const float *row, *W1, *B1, *W2, *B2;
    if (blk < N) { row = &g_h[blk * HD];        W1 = w1;  B1 = b1;  W2 = w2;  B2 = b2;  }
    else         { row = &g_e[(blk - N) * HD];  W1 = cw1; B1 = cb1; W2 = cw2; B2 = cb2; }
    in[t] = row[t]; in[t + 64] = row[t + 64];
    __syncthreads();
    float acc = B1[t];
#pragma unroll 8
    for (int k = 0; k < HD; k++) acc = fmaf(in[k], W1[k * 64 + t], acc);
    acc = acc > 0.f ? acc : 0.f;
    red[t] = acc * W2[t];
    __syncthreads();
#pragma unroll
    for (int o = 32; o > 0; o >>= 1) { if (t < o) red[t] += red[t + o]; __syncthreads(); }
    if (t == 0) {
        float o = red[0] + B2[0];
        if (blk < N) g_onsite[blk] = o; else g_coup[blk - N] = o;
    }
}

// dna mask + local dna-index per graph (serial scan over <=2048 nodes in smem)
__global__ void k_dna(const float* __restrict__ x, const int* __restrict__ batch, int N) {
    __shared__ int mi[N_MAX];
    __shared__ int bt[N_MAX];
    __shared__ int lo[N_MAX];
    int t = threadIdx.x;
    for (int n = t; n < N; n += blockDim.x) {
        float a = x[n * 4], b = x[n * 4 + 1], c = x[n * 4 + 2], d = x[n * 4 + 3];
        int dna = (a != 0.f || b != 0.f || c != 0.f || d != 0.f) ? 1 : 0;
        mi[n] = dna;
        g_dna[n] = dna;
        bt[n] = batch[n];
    }
    __syncthreads();
    if (t == 0) {
        int cum = 0, curb = -1, gstart = 0;
        for (int n = 0; n < N; n++) {
            int b = bt[n];
            if (b != curb) { curb = b; gstart = cum; }
            lo[n] = cum - gstart;
            cum += mi[n];
        }
    }
    __syncthreads();
    for (int n = t; n < N; n += blockDim.x) g_loc[n] = lo[n];
}

__global__ void k_hinit(float* __restrict__ H, int B) {
    int idx = blockIdx.x * blockDim.x + threadIdx.x;
    if (idx >= B * HS * HS) return;
    int r = (idx % (HS * HS)) / HS, c = idx % HS;
    H[idx] = (r == c) ? 1e-6f : 0.f;
}

__global__ void k_hdiag(const int* __restrict__ batch, float* __restrict__ H, int N) {
    int n = blockIdx.x * blockDim.x + threadIdx.x;
    if (n >= N) return;
    if (g_dna[n]) {
        int b = batch[n], l = g_loc[n];
        H[b * HS * HS + l * HS + l] += g_onsite[n];
    }
}

__global__ void k_hedge(const int* __restrict__ src, const int* __restrict__ dst,
                        const int* __restrict__ batch, float* __restrict__ H, int E) {
    int e = blockIdx.x * blockDim.x + threadIdx.x;
    if (e >= E) return;
    int s = src[e], d = dst[e];
    if (g_dna[s] && g_dna[d]) {
        int b = batch[s], u = g_loc[s], v = g_loc[d];
        float cv = g_coup[e];
        atomicAdd(&H[b * HS * HS + u * HS + v], cv);
        atomicAdd(&H[b * HS * HS + v * HS + u], cv);
    }
}

// ---------------- NEGF: one CTA per (graph, energy) ------------------------
// Gr = inv(A + i*D). Rank-8 blocked, unpivoted complex Gauss-Jordan.
// W in registers: 512 threads x (16 rows x 2 complex cols). Scalar FFMA update
// (proven fastest); panels through smem; phase 3 uses all 512 threads.
#define NB    8
#define NBLK  (HS / NB)
#define NTHR  512

// complex fma: m -= c * r
#define CFMS(m, c, r) do { \
    m.x = fmaf(-(c).x, (r).x, fmaf((c).y, (r).y, m.x)); \
    m.y = fmaf(-(c).x, (r).y, fmaf(-(c).y, (r).x, m.y)); \
} while (0)
#define CMUL(o, a, b) do { \
    o.x = (a).x * (b).x - (a).y * (b).y; \
    o.y = (a).x * (b).y + (a).y * (b).x; \
} while (0)

__global__ void __launch_bounds__(NTHR, 1) k_negf(
    const float* __restrict__ GL, const float* __restrict__ GR,
    const float* __restrict__ Hin, float* __restrict__ Tout,
    float* __restrict__ Dout) {
    __shared__ float2 Cs[HS][NB];        // column panel W[:,K]          8KB
    __shared__ float4 Rs[NB][64];        // row panel, packed col pairs  8KB
    __shared__ float2 Ws[NB][HS];        // old K-rows staging           8KB
    __shared__ float2 Pb[NB][NB];
    __shared__ float  glv[HS], grv[HS];
    __shared__ float  rsum[16], rtr[16];

    int tid  = threadIdx.x;
    int fc   = tid & 63;                 // owns complex cols 2fc, 2fc+1
    int rq   = tid >> 6;                 // owns rows rq*16 .. rq*16+15
    int warp = tid >> 5, lane = tid & 31;
    int b = blockIdx.x / NEG, ei = blockIdx.x % NEG;
    float Eg = (float)(-3.0 + 6.0 * (double)ei / 99.0);
    const float2* Hb2 = (const float2*)(Hin + (size_t)b * HS * HS);

    if (tid < HS) {
        glv[tid] = GL[b * HS + tid];
        grv[tid] = GR[b * HS + tid];
    }
    __syncthreads();

    // W = A + i*D in registers: w[ii][c] = elem (rq*16+ii, 2fc+c)
    float2 w[16][2];
#pragma unroll
    for (int ii = 0; ii < 16; ii++) {
        int i = rq * 16 + ii;
        float2 hv = Hb2[i * 64 + fc];
        float dvi = 0.5f * (glv[i] + grv[i]) + 1e-12f;
        int j0 = 2 * fc;
        w[ii][0] = make_float2(((i == j0)     ? Eg : 0.f) - hv.x,
                               (i == j0)     ? dvi : 0.f);
        w[ii][1] = make_float2(((i == j0 + 1) ? Eg : 0.f) - hv.y,
                               (i == j0 + 1) ? dvi : 0.f);
    }

    for (int kb = 0; kb < NBLK; kb++) {
        int c0 = kb * NB;
        bool blockcol = ((fc >> 2) == kb);      // owns cols inside block K
        bool krows = (rq == (kb >> 1));         // owns rows inside block K
        int base = (kb & 1) * 8;

        // ---- phase 1: column panel C = W[:,K]; stage old K-rows -----------
        if (blockcol) {
            int q0 = (fc & 3) * 2;
#pragma unroll
            for (int ii = 0; ii < 16; ii++) {
                int i = rq * 16 + ii;
                Cs[i][q0]     = w[ii][0];
                Cs[i][q0 + 1] = w[ii][1];
            }
        }
        if (krows) {
#pragma unroll
            for (int p = 0; p < NB; p++) {
                Ws[p][2 * fc]     = w[base + p][0];
                Ws[p][2 * fc + 1] = w[base + p][1];
            }
        }
        __syncthreads();

        // ---- phase 2: Pinv (8x8) by warp 0 --------------------------------
        if (warp == 0) {
#pragma unroll
            for (int e2 = 0; e2 < 2; e2++) {
                int e = lane + e2 * 32;
                Pb[e >> 3][e & 7] = Ws[e >> 3][c0 + (e & 7)];
            }
            __syncwarp();
            for (int kk = 0; kk < NB; kk++) {
                float2 pv = Pb[kk][kk];
                float inv = 1.f / fmaf(pv.x, pv.x, pv.y * pv.y);
                float2 ip = make_float2(pv.x * inv, -pv.y * inv);
                float2 nv[2];
#pragma unroll
                for (int e2 = 0; e2 < 2; e2++) {
                    int e = lane + e2 * 32, r = e >> 3, c = e & 7;
                    float2 old  = Pb[r][c];
                    float2 rowk = Pb[kk][c];
                    float2 colk = Pb[r][kk];
                    if (r == kk && c == kk) nv[e2] = ip;
                    else if (r == kk)       { CMUL(nv[e2], rowk, ip); }
                    else if (c == kk) {
                        float2 t; CMUL(t, colk, ip);
                        nv[e2] = make_float2(-t.x, -t.y);
                    } else {
                        float2 kr; CMUL(kr, rowk, ip);
                        nv[e2] = old; CFMS(nv[e2], colk, kr);
                    }
                }
                __syncwarp();
#pragma unroll
                for (int e2 = 0; e2 < 2; e2++) {
                    int e = lane + e2 * 32;
                    Pb[e >> 3][e & 7] = nv[e2];
                }
                __syncwarp();
            }
        }
        __syncthreads();

        // ---- phase 3: row panel R = Pinv * Wold[K,:], all threads (q=rq) --
        {
            int q = rq;
            float2 a0, a1;
            if (blockcol) {
                int jj = (fc & 3) * 2;
                a0 = Pb[q][jj]; a1 = Pb[q][jj + 1];
            } else {
                a0 = make_float2(0.f, 0.f); a1 = make_float2(0.f, 0.f);
#pragma unroll
                for (int p = 0; p < NB; p++) {
                    float2 pi = Pb[q][p];
                    float2 u0 = Ws[p][2 * fc], u1 = Ws[p][2 * fc + 1];
                    a0.x = fmaf(pi.x, u0.x, fmaf(-pi.y, u0.y, a0.x));
                    a0.y = fmaf(pi.x, u0.y, fmaf( pi.y, u0.x, a0.y));
                    a1.x = fmaf(pi.x, u1.x, fmaf(-pi.y, u1.y, a1.x));
                    a1.y = fmaf(pi.x, u1.y, fmaf( pi.y, u1.x, a1.y));
                }
            }
            Rs[q][fc] = make_float4(a0.x, a0.y, a1.x, a1.y);
        }
        __syncthreads();

        // ---- phase 4: rank-8 update on register tile (scalar FFMA) --------
        float4 r4[NB];
#pragma unroll
        for (int q = 0; q < NB; q++) r4[q] = Rs[q][fc];

#pragma unroll
        for (int ii = 0; ii < 16; ii++) {
            float2 m0, m1;
            if (blockcol) { m0 = make_float2(0.f, 0.f); m1 = make_float2(0.f, 0.f); }
            else          { m0 = w[ii][0]; m1 = w[ii][1]; }
            const float4* crow = (const float4*)&Cs[rq * 16 + ii][0];
#pragma unroll
            for (int qq = 0; qq < 4; qq++) {
                float4 cp = crow[qq];               // 2 complex C values
                float2 ca = make_float2(cp.x, cp.y);
                float2 cb = make_float2(cp.z, cp.w);
                float4 ra = r4[qq * 2], rb = r4[qq * 2 + 1];
                float2 ra0 = make_float2(ra.x, ra.y), ra1 = make_float2(ra.z, ra.w);
                float2 rb0 = make_float2(rb.x, rb.y), rb1 = make_float2(rb.z, rb.w);
                CFMS(m0, ca, ra0); CFMS(m1, ca, ra1);
                CFMS(m0, cb, rb0); CFMS(m1, cb, rb1);
            }
            w[ii][0] = m0; w[ii][1] = m1;
        }
        if (krows) {                                // K rows get R (incl. Pinv)
#pragma unroll
            for (int q = 0; q < NB; q++) {
                float4 rr = r4[q];
                w[base + q][0] = make_float2(rr.x, rr.y);
                w[base + q][1] = make_float2(rr.z, rr.w);
            }
        }
        __syncthreads();
    }

    // ---- outputs: T = sum_ij GL_i |G_ij|^2 GR_j ; dos = -tr(Im G)/pi ------
    float tpart = 0.f, dpart = 0.f;
    int j0 = 2 * fc;
    float gr0 = grv[j0], gr1 = grv[j0 + 1];
#pragma unroll
    for (int ii = 0; ii < 16; ii++) {
        int i = rq * 16 + ii;
        float2 g0 = w[ii][0], g1 = w[ii][1];
        tpart += glv[i] * (gr0 * fmaf(g0.x, g0.x, g0.y * g0.y) +
                           gr1 * fmaf(g1.x, g1.x, g1.y * g1.y));
        if (i == j0)     dpart += g0.y;
        if (i == j0 + 1) dpart += g1.y;
    }
#pragma unroll
    for (int o = 16; o > 0; o >>= 1) {
        tpart += __shfl_down_sync(0xffffffffu, tpart, o);
        dpart += __shfl_down_sync(0xffffffffu, dpart, o);
    }
    if (lane == 0) { rsum[warp] = tpart; rtr[warp] = dpart; }
    __syncthreads();
    if (tid == 0) {
        float ts = 0.f, tr = 0.f;
#pragma unroll
        for (int ww = 0; ww < 16; ww++) { ts += rsum[ww]; tr += rtr[ww]; }
        Tout[b * NEG + ei] = log10f(fmaxf(ts, 1e-16f));
        Dout[b * NEG + ei] = log10f(fmaxf(-tr / 3.14159265358979323846f, 1e-16f));
    }
}

// ---------------- launch ----------------------------------------------------
extern "C" void kernel_launch(void* const* d_in, const int* in_sizes, int n_in,
                              void* d_out, int out_size) {
    const float* x      = (const float*)d_in[0];
    const int*   ei     = (const int*)  d_in[1];
    const float* ea     = (const float*)d_in[2];
    const int*   batch  = (const int*)  d_in[3];
    const float* GL     = (const float*)d_in[4];
    const float* GR     = (const float*)d_in[5];
    const float* node_w = (const float*)d_in[6];
    const float* node_b = (const float*)d_in[7];
    const float* edgep_w= (const float*)d_in[8];
    const float* edgep_b= (const float*)d_in[9];
    const float* gat_lin= (const float*)d_in[10];
    const float* att_src= (const float*)d_in[11];
    const float* att_dst= (const float*)d_in[12];
    const float* gat_le = (const float*)d_in[13];
    const float* att_ed = (const float*)d_in[14];
    const float* gat_b  = (const float*)d_in[15];
    const float* ln_s   = (const float*)d_in[16];
    const float* ln_b   = (const float*)d_in[17];
    const float* on_w1  = (const float*)d_in[18];
    const float* on_b1  = (const float*)d_in[19];
    const float* on_w2  = (const float*)d_in[20];
    const float* on_b2  = (const float*)d_in[21];
    const float* cp_w1  = (const float*)d_in[22];
    const float* cp_b1  = (const float*)d_in[23];
    const float* cp_w2  = (const float*)d_in[24];
    const float* cp_b2  = (const float*)d_in[25];

    int N = in_sizes[0] / 4;
    int E = in_sizes[2] / 5;
    int B = in_sizes[4] / HS;
    const int* src = ei;
    const int* dst = ei + E;

    float* out  = (float*)d_out;
    float* Tout = out;
    float* Dout = out + B * NEG;
    float* Hout = out + 2 * B * NEG;

    k_init_h<<<N, HD>>>(x, node_w, node_b);
    k_init_e<<<E, HD>>>(ea, edgep_w, edgep_b);

    int nb_n = (N + 3) / 4, nb_e = (E + 3) / 4;
    int smax = 2 * N * HEADS * (int)sizeof(float);
    for (int l = 0; l < NLAYER; l++) {
        k_attn   <<<nb_n + nb_e, HD>>>(gat_lin + l * HD * HD, att_src + l * HEADS * CDIM,
                                       att_dst + l * HEADS * CDIM, gat_le + l * HD * HD,
                                       att_ed + l * HEADS * CDIM, N, E, nb_n);
        k_softmax<<<1, 1024, smax>>>(src, dst, N, E);
        k_agg    <<<E + N, HD>>>(src, dst, N, E);
        k_ln     <<<N, HD>>>(gat_b + l * HD, ln_s + l * HD, ln_b + l * HD);
    }

    k_mlp  <<<N + E, 64>>>(on_w1, on_b1, on_w2, on_b2, cp_w1, cp_b1, cp_w2, cp_b2, N);
    k_dna  <<<1, 1024>>>(x, batch, N);
    k_hinit<<<(B * HS * HS + 255) / 256, 256>>>(Hout, B);
    k_hdiag<<<(N + 255) / 256, 256>>>(batch, Hout, N);
    k_hedge<<<(E + 255) / 256, 256>>>(src, dst, batch, Hout, E);

    k_negf<<<B * NEG, NTHR>>>(GL, GR, Hout, Tout, Dout);
}

// round 7
// speedup vs baseline: 3.2123x; 2.5583x over previous
#include <cuda_runtime.h>
#include <math.h>

#define HD     128
#define HEADS  4
#define CDIM   32
#define NLAYER 4
#define NEG    100
#define HS     128

#define N_MAX  2048
#define E_MAX  4096
#define F_MAX  (N_MAX + E_MAX)
#define B_MAX  32
#define BE_MAX (B_MAX * NEG)

// ---------------- scratch (device globals; no allocation allowed) ----------
__device__ float g_h   [N_MAX * HD];
__device__ float g_e   [E_MAX * HD];
__device__ float g_xl  [N_MAX * HD];
__device__ float g_ssrc[N_MAX * HEADS];
__device__ float g_sdst[N_MAX * HEADS];
__device__ float g_ae  [E_MAX * HEADS];
__device__ float g_aesum[HEADS];
__device__ float g_ex   [F_MAX * HEADS];
__device__ float g_den  [N_MAX * HEADS];
__device__ float g_agg  [N_MAX * HD];
__device__ float g_onsite[N_MAX];
__device__ float g_coup  [E_MAX];
__device__ int   g_dna  [N_MAX];
__device__ int   g_loc  [N_MAX];
// NEGF scratch
__device__ float g_hbd[B_MAX * HS];      // H diag
__device__ float g_hb1[B_MAX * HS];      // H super-1
__device__ float g_hb2[B_MAX * HS];      // H super-2
__device__ float g_dvb[B_MAX * HS];      // D diag
__device__ float2 g_lu[BE_MAX * 5 * HS]; // a,b,e,f,dinv bands per (b,e)
__device__ float g_Tacc[BE_MAX];
__device__ float g_Dacc[BE_MAX];

// ---------------- small helpers -------------------------------------------
__device__ __forceinline__ void atomicMaxFS(float* addr, float val) {
    int* ia = (int*)addr;
    int old = *ia;
    while (__int_as_float(old) < val) {
        int assumed = old;
        old = atomicCAS(ia, assumed, __float_as_int(val));
        if (old == assumed) break;
    }
}

// complex mul / fms helpers
#define CMUL(o, a, b) do { \
    (o).x = (a).x * (b).x - (a).y * (b).y; \
    (o).y = (a).x * (b).y + (a).y * (b).x; \
} while (0)
#define CFMS(m, c, r) do { \
    (m).x = fmaf(-(c).x, (r).x, fmaf((c).y, (r).y, (m).x)); \
    (m).y = fmaf(-(c).x, (r).y, fmaf(-(c).y, (r).x, (m).y)); \
} while (0)

// ---------------- GNN kernels ----------------------------------------------
__global__ void k_init_h(const float* __restrict__ x, const float* __restrict__ w,
                         const float* __restrict__ b) {
    int n = blockIdx.x, t = threadIdx.x;
    float acc = b[t];
#pragma unroll
    for (int k = 0; k < 4; k++) acc = fmaf(x[n * 4 + k], w[k * HD + t], acc);
    g_h[n * HD + t] = acc;
    g_agg[n * HD + t] = 0.f;
    if (n == 0 && t < HEADS) g_aesum[t] = 0.f;
}

__global__ void k_init_e(const float* __restrict__ ea, const float* __restrict__ w,
                         const float* __restrict__ b) {
    int n = blockIdx.x, t = threadIdx.x;
    float acc = b[t];
#pragma unroll
    for (int k = 0; k < 5; k++) acc = fmaf(ea[n * 5 + k], w[k * HD + t], acc);
    g_e[n * HD + t] = acc;
}

// fused xl (nodes) + edge-attention projection: 4 rows per block
__global__ void k_attn(const float* __restrict__ Wn, const float* __restrict__ asrc,
                       const float* __restrict__ adst, const float* __restrict__ We,
                       const float* __restrict__ aedge, int N, int E, int nb_n) {
    __shared__ float rows[4][HD];
    __shared__ float outs[4][HD];
    int t = threadIdx.x;
    bool isnode = (blockIdx.x < nb_n);
    int r0 = (isnode ? blockIdx.x : blockIdx.x - nb_n) * 4;
    int cnt = (isnode ? N : E) - r0; if (cnt > 4) cnt = 4;
    const float* base = isnode ? g_h : g_e;
    const float* W = isnode ? Wn : We;
#pragma unroll
    for (int rr = 0; rr < 4; rr++)
        rows[rr][t] = (rr < cnt) ? base[(r0 + rr) * HD + t] : 0.f;
    __syncthreads();
    float a0 = 0.f, a1 = 0.f, a2 = 0.f, a3 = 0.f;
#pragma unroll 4
    for (int k = 0; k < HD; k++) {
        float wv = W[k * HD + t];
        a0 = fmaf(rows[0][k], wv, a0);
        a1 = fmaf(rows[1][k], wv, a1);
        a2 = fmaf(rows[2][k], wv, a2);
        a3 = fmaf(rows[3][k], wv, a3);
    }
    outs[0][t] = a0; outs[1][t] = a1; outs[2][t] = a2; outs[3][t] = a3;
    if (isnode) {
        if (0 < cnt) g_xl[(r0 + 0) * HD + t] = a0;
        if (1 < cnt) g_xl[(r0 + 1) * HD + t] = a1;
        if (2 < cnt) g_xl[(r0 + 2) * HD + t] = a2;
        if (3 < cnt) g_xl[(r0 + 3) * HD + t] = a3;
    }
    __syncthreads();
    int w = t >> 5, lane = t & 31;
    if (w < cnt) {
        if (isnode) {
#pragma unroll
            for (int h = 0; h < HEADS; h++) {
                float x = outs[w][h * 32 + lane];
                float vs = x * asrc[h * 32 + lane];
                float vd = x * adst[h * 32 + lane];
#pragma unroll
                for (int o = 16; o > 0; o >>= 1) {
                    vs += __shfl_down_sync(0xffffffffu, vs, o);
                    vd += __shfl_down_sync(0xffffffffu, vd, o);
                }
                if (lane == 0) {
                    g_ssrc[(r0 + w) * HEADS + h] = vs;
                    g_sdst[(r0 + w) * HEADS + h] = vd;
                }
            }
        } else {
#pragma unroll
            for (int h = 0; h < HEADS; h++) {
                float v = outs[w][h * 32 + lane] * aedge[h * 32 + lane];
#pragma unroll
                for (int o = 16; o > 0; o >>= 1) v += __shfl_down_sync(0xffffffffu, v, o);
                if (lane == 0) {
                    g_ae[(r0 + w) * HEADS + h] = v;
                    atomicAdd(&g_aesum[h], v);
                }
            }
        }
    }
}

// fused alpha + segment-max + exp + segment-sum: single CTA, smem accumulators
__global__ void k_softmax(const int* __restrict__ src, const int* __restrict__ dst,
                          int N, int E) {
    extern __shared__ float sm[];
    float* m_s = sm;
    float* d_s = sm + N * HEADS;
    int t = threadIdx.x, NT = blockDim.x;
    int NH = N * HEADS, F = E + N;
    float av[24];                        // per-thread alpha cache
    for (int i = t; i < NH; i += NT) { m_s[i] = -3.0e38f; d_s[i] = 0.f; }
    __syncthreads();
    int kk = 0;
    for (int idx = t; idx < F * HEADS; idx += NT, kk++) {
        int f = idx >> 2, hh = idx & 3;
        int s, d; float ae;
        if (f < E) { s = src[f]; d = dst[f]; ae = g_ae[f * HEADS + hh]; }
        else       { s = f - E; d = s;       ae = g_aesum[hh] / (float)E; }
        float a = g_ssrc[s * HEADS + hh] + g_sdst[d * HEADS + hh] + ae;
        a = a > 0.f ? a : 0.2f * a;
        av[kk] = a;
        atomicMaxFS(&m_s[d * HEADS + hh], a);
    }
    __syncthreads();
    kk = 0;
    for (int idx = t; idx < F * HEADS; idx += NT, kk++) {
        int f = idx >> 2, hh = idx & 3;
        int d = (f < E) ? dst[f] : (f - E);
        float ex = expf(av[kk] - m_s[d * HEADS + hh]);
        g_ex[idx] = ex;
        atomicAdd(&d_s[d * HEADS + hh], ex);
    }
    __syncthreads();
    for (int i = t; i < NH; i += NT) g_den[i] = d_s[i];
}

__global__ void k_agg(const int* __restrict__ src, const int* __restrict__ dst,
                      int N, int E) {
    int f = blockIdx.x, t = threadIdx.x;
    int s, d;
    if (f < E) { s = src[f]; d = dst[f]; }
    else       { s = f - E;  d = s; }
    int hh = t >> 5;
    float w = g_ex[f * HEADS + hh] / g_den[d * HEADS + hh];
    atomicAdd(&g_agg[d * HD + t], g_xl[s * HD + t] * w);
}

// layernorm(relu(agg+bias) + h) and zero accumulators for the next layer
__global__ void k_ln(const float* __restrict__ bias, const float* __restrict__ s,
                     const float* __restrict__ bb) {
    __shared__ float red[HD];
    int n = blockIdx.x, t = threadIdx.x;
    float v = g_agg[n * HD + t] + bias[t];
    g_agg[n * HD + t] = 0.f;
    v = v > 0.f ? v : 0.f;
    v += g_h[n * HD + t];
    red[t] = v; __syncthreads();
#pragma unroll
    for (int o = 64; o > 0; o >>= 1) { if (t < o) red[t] += red[t + o]; __syncthreads(); }
    float mu = red[0] / (float)HD;
    __syncthreads();
    float dd = v - mu;
    red[t] = dd * dd; __syncthreads();
#pragma unroll
    for (int o = 64; o > 0; o >>= 1) { if (t < o) red[t] += red[t + o]; __syncthreads(); }
    float var = red[0] / (float)HD;
    g_h[n * HD + t] = dd * rsqrtf(var + 1e-5f) * s[t] + bb[t];
    if (n == 0 && t < HEADS) g_aesum[t] = 0.f;
}

// onsite (nodes) + coupling (edges) MLPs: 128 -> 64 (relu) -> 1
__global__ void k_mlp(const float* __restrict__ w1, const float* __restrict__ b1,
                      const float* __restrict__ w2, const float* __restrict__ b2,
                      const float* __restrict__ cw1, const float* __restrict__ cb1,
                      const float* __restrict__ cw2, const float* __restrict__ cb2,
                      int N) {
    __shared__ float in[HD];
    __shared__ float red[64];
    int blk = blockIdx.x, t = threadIdx.x;
    const float *row, *W1, *B1, *W2, *B2;
    if (blk < N) { row = &g_h[blk * HD];        W1 = w1;  B1 = b1;  W2 = w2;  B2 = b2;  }
    else         { row = &g_e[(blk - N) * HD];  W1 = cw1; B1 = cb1; W2 = cw2; B2 = cb2; }
    in[t] = row[t]; in[t + 64] = row[t + 64];
    __syncthreads();
    float acc = B1[t];
#pragma unroll 8
    for (int k = 0; k < HD; k++) acc = fmaf(in[k], W1[k * 64 + t], acc);
    acc = acc > 0.f ? acc : 0.f;
    red[t] = acc * W2[t];
    __syncthreads();
#pragma unroll
    for (int o = 32; o > 0; o >>= 1) { if (t < o) red[t] += red[t + o]; __syncthreads(); }
    if (t == 0) {
        float o = red[0] + B2[0];
        if (blk < N) g_onsite[blk] = o; else g_coup[blk - N] = o;
    }
}

// dna mask + local dna-index per graph (serial scan over <=2048 nodes in smem)
__global__ void k_dna(const float* __restrict__ x, const int* __restrict__ batch, int N) {
    __shared__ int mi[N_MAX];
    __shared__ int bt[N_MAX];
    __shared__ int lo[N_MAX];
    int t = threadIdx.x;
    for (int n = t; n < N; n += blockDim.x) {
        float a = x[n * 4], b = x[n * 4 + 1], c = x[n * 4 + 2], d = x[n * 4 + 3];
        int dna = (a != 0.f || b != 0.f || c != 0.f || d != 0.f) ? 1 : 0;
        mi[n] = dna;
        g_dna[n] = dna;
        bt[n] = batch[n];
    }
    __syncthreads();
    if (t == 0) {
        int cum = 0, curb = -1, gstart = 0;
        for (int n = 0; n < N; n++) {
            int b = bt[n];
            if (b != curb) { curb = b; gstart = cum; }
            lo[n] = cum - gstart;
            cum += mi[n];
        }
    }
    __syncthreads();
    for (int n = t; n < N; n += blockDim.x) g_loc[n] = lo[n];
}

__global__ void k_hinit(float* __restrict__ H, int B) {
    int idx = blockIdx.x * blockDim.x + threadIdx.x;
    if (idx >= B * HS * HS) return;
    int r = (idx % (HS * HS)) / HS, c = idx % HS;
    H[idx] = (r == c) ? 1e-6f : 0.f;
}

__global__ void k_hdiag(const int* __restrict__ batch, float* __restrict__ H, int N) {
    int n = blockIdx.x * blockDim.x + threadIdx.x;
    if (n >= N) return;
    if (g_dna[n]) {
        int b = batch[n], l = g_loc[n];
        H[b * HS * HS + l * HS + l] += g_onsite[n];
    }
}

__global__ void k_hedge(const int* __restrict__ src, const int* __restrict__ dst,
                        const int* __restrict__ batch, float* __restrict__ H, int E) {
    int e = blockIdx.x * blockDim.x + threadIdx.x;
    if (e >= E) return;
    int s = src[e], d = dst[e];
    if (g_dna[s] && g_dna[d]) {
        int b = batch[s], u = g_loc[s], v = g_loc[d];
        float cv = g_coup[e];
        atomicAdd(&H[b * HS * HS + u * HS + v], cv);
        atomicAdd(&H[b * HS * HS + v * HS + u], cv);
    }
}

// ---------------- NEGF: banded (pentadiagonal) solver ----------------------
// H is pentadiagonal by construction (chain graphs with +/-1, +/-2 couplings;
// contact edges masked by dna). M = Eg*I - H + i*D -> banded LU (unpivoted;
// same Schur complements as the dense unpivoted elimination used before) +
// per-column forward/backward substitution.

// extract the 3 bands of H + the D diagonal per graph
__global__ void k_bands(const float* __restrict__ H, const float* __restrict__ GL,
                        const float* __restrict__ GR) {
    int b = blockIdx.x, t = threadIdx.x;
    const float* Hb = H + (size_t)b * HS * HS;
    g_hbd[b * HS + t] = Hb[t * HS + t];
    g_hb1[b * HS + t] = (t < HS - 1) ? Hb[t * HS + t + 1] : 0.f;
    g_hb2[b * HS + t] = (t < HS - 2) ? Hb[t * HS + t + 2] : 0.f;
    g_dvb[b * HS + t] = 0.5f * (GL[b * HS + t] + GR[b * HS + t]) + 1e-12f;
}

// banded LU: one thread per (b,e); writes a,b,e,f,dinv bands to g_lu
__global__ void k_lu(int BE) {
    int be = blockIdx.x * blockDim.x + threadIdx.x;
    if (be >= BE) return;
    int b = be / NEG, e = be % NEG;
    float Eg = (float)(-3.0 + 6.0 * (double)e / 99.0);
    const float* hd = g_hbd + b * HS;
    const float* h1 = g_hb1 + b * HS;
    const float* h2 = g_hb2 + b * HS;
    const float* dv = g_dvb + b * HS;
    float2* out = g_lu + (size_t)be * 5 * HS;
    g_Tacc[be] = 0.f; g_Dacc[be] = 0.f;

    float2 e1 = {0.f, 0.f}, e2 = {0.f, 0.f};
    float2 f1 = {0.f, 0.f}, f2 = {0.f, 0.f};
    float2 di1 = {0.f, 0.f}, di2 = {0.f, 0.f};
    for (int i = 0; i < HS; i++) {
        float2 Mi = make_float2(Eg - hd[i], dv[i]);
        float m1 = (i >= 1) ? -h1[i - 1] : 0.f;
        float m2 = (i >= 2) ? -h2[i - 2] : 0.f;
        float2 bi = make_float2(m2 * di2.x, m2 * di2.y);
        float2 tt = make_float2(m1, 0.f);
        CFMS(tt, bi, e2);                          // m1 - bi*e2
        float2 ai; CMUL(ai, tt, di1);              // / d_{i-1}
        float2 d = Mi;
        CFMS(d, bi, f2);
        CFMS(d, ai, e1);
        float2 ei = make_float2(0.f, 0.f);
        if (i < HS - 1) { ei = make_float2(-h1[i], 0.f); CFMS(ei, ai, f1); }
        float2 fi = make_float2((i < HS - 2) ? -h2[i] : 0.f, 0.f);
        float inv = 1.f / fmaf(d.x, d.x, d.y * d.y);
        float2 dinv = make_float2(d.x * inv, -d.y * inv);
        out[0 * HS + i] = ai;
        out[1 * HS + i] = bi;
        out[2 * HS + i] = ei;
        out[3 * HS + i] = fi;
        out[4 * HS + i] = dinv;
        e2 = e1; e1 = ei; f2 = f1; f1 = fi; di2 = di1; di1 = dinv;
    }
}

// column solves: one warp-CTA per (b,e, quarter); lane = column j
__global__ void __launch_bounds__(32) k_solve(
    const float* __restrict__ GL, const float* __restrict__ GR, int BE) {
    __shared__ float2 ys[HS * 32];       // 32KB: per-lane y history
    __shared__ float2 sa[HS], sb[HS], se[HS], sf[HS], sdi[HS];
    __shared__ float  sgl[HS], sgr[HS];
    int blk = blockIdx.x;
    int be = blk >> 2, q = blk & 3;
    int b = be / NEG;
    int lane = threadIdx.x;
    const float2* lu = g_lu + (size_t)be * 5 * HS;
#pragma unroll
    for (int k = 0; k < 4; k++) {
        int i = lane + k * 32;
        sa[i]  = lu[0 * HS + i];
        sb[i]  = lu[1 * HS + i];
        se[i]  = lu[2 * HS + i];
        sf[i]  = lu[3 * HS + i];
        sdi[i] = lu[4 * HS + i];
        sgl[i] = GL[b * HS + i];
        sgr[i] = GR[b * HS + i];
    }
    __syncwarp();

    int j = q * 32 + lane;
    int i0 = q * 32;
    // forward: L y = e_j (y_i = 0 for i < i0 <= j)
    float2 y1 = {0.f, 0.f}, y2 = {0.f, 0.f};
    for (int i = i0; i < HS; i++) {
        float2 y = make_float2((i == j) ? 1.f : 0.f, 0.f);
        CFMS(y, sa[i], y1);
        CFMS(y, sb[i], y2);
        ys[i * 32 + lane] = y;
        y2 = y1; y1 = y;
    }
    // backward: U x = y ; accumulate sum_i gl_i |x_i|^2 and Im x_jj
    float2 x1 = {0.f, 0.f}, x2 = {0.f, 0.f};
    float tp = 0.f, dj = 0.f;
    for (int i = HS - 1; i >= 0; i--) {
        float2 t = (i >= i0) ? ys[i * 32 + lane] : make_float2(0.f, 0.f);
        CFMS(t, se[i], x1);
        CFMS(t, sf[i], x2);
        float2 x; CMUL(x, t, sdi[i]);
        tp = fmaf(sgl[i], fmaf(x.x, x.x, x.y * x.y), tp);
        if (i == j) dj = x.y;
        x2 = x1; x1 = x;
    }
    tp *= sgr[j];
#pragma unroll
    for (int o = 16; o > 0; o >>= 1) {
        tp += __shfl_down_sync(0xffffffffu, tp, o);
        dj += __shfl_down_sync(0xffffffffu, dj, o);
    }
    if (lane == 0) {
        atomicAdd(&g_Tacc[be], tp);
        atomicAdd(&g_Dacc[be], dj);
    }
}

__global__ void k_finish(float* __restrict__ Tout, float* __restrict__ Dout, int BE) {
    int be = blockIdx.x * blockDim.x + threadIdx.x;
    if (be >= BE) return;
    Tout[be] = log10f(fmaxf(g_Tacc[be], 1e-16f));
    Dout[be] = log10f(fmaxf(-g_Dacc[be] / 3.14159265358979323846f, 1e-16f));
}

// ---------------- launch ----------------------------------------------------
extern "C" void kernel_launch(void* const* d_in, const int* in_sizes, int n_in,
                              void* d_out, int out_size) {
    const float* x      = (const float*)d_in[0];
    const int*   ei     = (const int*)  d_in[1];
    const float* ea     = (const float*)d_in[2];
    const int*   batch  = (const int*)  d_in[3];
    const float* GL     = (const float*)d_in[4];
    const float* GR     = (const float*)d_in[5];
    const float* node_w = (const float*)d_in[6];
    const float* node_b = (const float*)d_in[7];
    const float* edgep_w= (const float*)d_in[8];
    const float* edgep_b= (const float*)d_in[9];
    const float* gat_lin= (const float*)d_in[10];
    const float* att_src= (const float*)d_in[11];
    const float* att_dst= (const float*)d_in[12];
    const float* gat_le = (const float*)d_in[13];
    const float* att_ed = (const float*)d_in[14];
    const float* gat_b  = (const float*)d_in[15];
    const float* ln_s   = (const float*)d_in[16];
    const float* ln_b   = (const float*)d_in[17];
    const float* on_w1  = (const float*)d_in[18];
    const float* on_b1  = (const float*)d_in[19];
    const float* on_w2  = (const float*)d_in[20];
    const float* on_b2  = (const float*)d_in[21];
    const float* cp_w1  = (const float*)d_in[22];
    const float* cp_b1  = (const float*)d_in[23];
    const float* cp_w2  = (const float*)d_in[24];
    const float* cp_b2  = (const float*)d_in[25];

    int N = in_sizes[0] / 4;
    int E = in_sizes[2] / 5;
    int B = in_sizes[4] / HS;
    int BE = B * NEG;
    const int* src = ei;
    const int* dst = ei + E;

    float* out  = (float*)d_out;
    float* Tout = out;
    float* Dout = out + BE;
    float* Hout = out + 2 * BE;

    k_init_h<<<N, HD>>>(x, node_w, node_b);
    k_init_e<<<E, HD>>>(ea, edgep_w, edgep_b);

    int nb_n = (N + 3) / 4, nb_e = (E + 3) / 4;
    int smax = 2 * N * HEADS * (int)sizeof(float);
    for (int l = 0; l < NLAYER; l++) {
        k_attn   <<<nb_n + nb_e, HD>>>(gat_lin + l * HD * HD, att_src + l * HEADS * CDIM,
                                       att_dst + l * HEADS * CDIM, gat_le + l * HD * HD,
                                       att_ed + l * HEADS * CDIM, N, E, nb_n);
        k_softmax<<<1, 1024, smax>>>(src, dst, N, E);
        k_agg    <<<E + N, HD>>>(src, dst, N, E);
        k_ln     <<<N, HD>>>(gat_b + l * HD, ln_s + l * HD, ln_b + l * HD);
    }

    k_mlp  <<<N + E, 64>>>(on_w1, on_b1, on_w2, on_b2, cp_w1, cp_b1, cp_w2, cp_b2, N);
    k_dna  <<<1, 1024>>>(x, batch, N);
    k_hinit<<<(B * HS * HS + 255) / 256, 256>>>(Hout, B);
    k_hdiag<<<(N + 255) / 256, 256>>>(batch, Hout, N);
    k_hedge<<<(E + 255) / 256, 256>>>(src, dst, batch, Hout, E);

    k_bands <<<B, HS>>>(Hout, GL, GR);
    k_lu    <<<(BE + 127) / 128, 128>>>(BE);
    k_solve <<<BE * 4, 32>>>(GL, GR, BE);
    k_finish<<<(BE + 127) / 128, 128>>>(Tout, Dout, BE);
}

// round 8
// speedup vs baseline: 4.0571x; 1.2630x over previous
#include <cuda_runtime.h>
#include <math.h>

#define HD     128
#define HEADS  4
#define CDIM   32
#define NLAYER 4
#define NEG    100
#define HS     128

#define N_MAX  2048
#define E_MAX  4096
#define F_MAX  (N_MAX + E_MAX)
#define B_MAX  32
#define BE_MAX (B_MAX * NEG)

// ---------------- scratch (device globals; no allocation allowed) ----------
__device__ float g_h   [N_MAX * HD];
__device__ float g_e   [E_MAX * HD];
__device__ float g_xl  [N_MAX * HD];
__device__ float g_ssrc[N_MAX * HEADS];
__device__ float g_sdst[N_MAX * HEADS];
__device__ float g_ae  [E_MAX * HEADS];
__device__ float g_aesum[HEADS];
__device__ float g_den  [N_MAX * HEADS];
__device__ float g_agg  [N_MAX * HD];
__device__ float g_onsite[N_MAX];
__device__ float g_coup  [E_MAX];
__device__ int   g_dna  [N_MAX];
__device__ int   g_loc  [N_MAX];
// NEGF scratch
__device__ float g_hbd[B_MAX * HS];      // H diag (onsite sums, no 1e-6)
__device__ float g_hb1[B_MAX * HS];      // H super-1
__device__ float g_hb2[B_MAX * HS];      // H super-2
__device__ float g_dvb[B_MAX * HS];      // D diag
__device__ float2 g_lu[BE_MAX * 5 * HS]; // a,b,e,f,dinv bands per (b,e)
__device__ float g_Tacc[BE_MAX];
__device__ float g_Dacc[BE_MAX];
__device__ int   g_cnt [BE_MAX];

// complex mul / fms helpers
#define CMUL(o, a, b) do { \
    (o).x = (a).x * (b).x - (a).y * (b).y; \
    (o).y = (a).x * (b).y + (a).y * (b).x; \
} while (0)
#define CFMS(m, c, r) do { \
    (m).x = fmaf(-(c).x, (r).x, fmaf((c).y, (r).y, (m).x)); \
    (m).y = fmaf(-(c).x, (r).y, fmaf(-(c).y, (r).x, (m).y)); \
} while (0)

// ---------------- GNN kernels ----------------------------------------------
__global__ void k_init_h(const float* __restrict__ x, const float* __restrict__ w,
                         const float* __restrict__ b) {
    int n = blockIdx.x, t = threadIdx.x;
    float acc = b[t];
#pragma unroll
    for (int k = 0; k < 4; k++) acc = fmaf(x[n * 4 + k], w[k * HD + t], acc);
    g_h[n * HD + t] = acc;
    g_agg[n * HD + t] = 0.f;
    if (t < HEADS) g_den[n * HEADS + t] = 0.f;
    if (n == 0 && t < HEADS) g_aesum[t] = 0.f;
}

__global__ void k_init_e(const float* __restrict__ ea, const float* __restrict__ w,
                         const float* __restrict__ b) {
    int n = blockIdx.x, t = threadIdx.x;
    float acc = b[t];
#pragma unroll
    for (int k = 0; k < 5; k++) acc = fmaf(ea[n * 5 + k], w[k * HD + t], acc);
    g_e[n * HD + t] = acc;
}

// fused xl (nodes) + edge-attention projection: 4 rows per block
__global__ void k_attn(const float* __restrict__ Wn, const float* __restrict__ asrc,
                       const float* __restrict__ adst, const float* __restrict__ We,
                       const float* __restrict__ aedge, int N, int E, int nb_n) {
    __shared__ float rows[4][HD];
    __shared__ float outs[4][HD];
    int t = threadIdx.x;
    bool isnode = (blockIdx.x < nb_n);
    int r0 = (isnode ? blockIdx.x : blockIdx.x - nb_n) * 4;
    int cnt = (isnode ? N : E) - r0; if (cnt > 4) cnt = 4;
    const float* base = isnode ? g_h : g_e;
    const float* W = isnode ? Wn : We;
#pragma unroll
    for (int rr = 0; rr < 4; rr++)
        rows[rr][t] = (rr < cnt) ? base[(r0 + rr) * HD + t] : 0.f;
    __syncthreads();
    float a0 = 0.f, a1 = 0.f, a2 = 0.f, a3 = 0.f;
#pragma unroll 4
    for (int k = 0; k < HD; k++) {
        float wv = W[k * HD + t];
        a0 = fmaf(rows[0][k], wv, a0);
        a1 = fmaf(rows[1][k], wv, a1);
        a2 = fmaf(rows[2][k], wv, a2);
        a3 = fmaf(rows[3][k], wv, a3);
    }
    outs[0][t] = a0; outs[1][t] = a1; outs[2][t] = a2; outs[3][t] = a3;
    if (isnode) {
        if (0 < cnt) g_xl[(r0 + 0) * HD + t] = a0;
        if (1 < cnt) g_xl[(r0 + 1) * HD + t] = a1;
        if (2 < cnt) g_xl[(r0 + 2) * HD + t] = a2;
        if (3 < cnt) g_xl[(r0 + 3) * HD + t] = a3;
    }
    __syncthreads();
    int w = t >> 5, lane = t & 31;
    if (w < cnt) {
        if (isnode) {
#pragma unroll
            for (int h = 0; h < HEADS; h++) {
                float x = outs[w][h * 32 + lane];
                float vs = x * asrc[h * 32 + lane];
                float vd = x * adst[h * 32 + lane];
#pragma unroll
                for (int o = 16; o > 0; o >>= 1) {
                    vs += __shfl_down_sync(0xffffffffu, vs, o);
                    vd += __shfl_down_sync(0xffffffffu, vd, o);
                }
                if (lane == 0) {
                    g_ssrc[(r0 + w) * HEADS + h] = vs;
                    g_sdst[(r0 + w) * HEADS + h] = vd;
                }
            }
        } else {
#pragma unroll
            for (int h = 0; h < HEADS; h++) {
                float v = outs[w][h * 32 + lane] * aedge[h * 32 + lane];
#pragma unroll
                for (int o = 16; o > 0; o >>= 1) v += __shfl_down_sync(0xffffffffu, v, o);
                if (lane == 0) {
                    g_ae[(r0 + w) * HEADS + h] = v;
                    atomicAdd(&g_aesum[h], v);
                }
            }
        }
    }
}

// fused attention-weight + aggregation (softmax shift cancels exactly):
// U[d] += xl[s]*exp(alpha), den[d] += exp(alpha); k_ln divides.
__global__ void k_edgeagg(const int* __restrict__ src, const int* __restrict__ dst,
                          int N, int E) {
    int f = blockIdx.x, t = threadIdx.x;
    int hh = t >> 5, lane = t & 31;
    int s, d; float ae;
    if (f < E) { s = src[f]; d = dst[f]; ae = g_ae[f * HEADS + hh]; }
    else       { s = f - E; d = s;       ae = g_aesum[hh] / (float)E; }
    float a = g_ssrc[s * HEADS + hh] + g_sdst[d * HEADS + hh] + ae;
    a = a > 0.f ? a : 0.2f * a;
    float ex = expf(a);
    atomicAdd(&g_agg[d * HD + t], g_xl[s * HD + t] * ex);
    if (lane == 0) atomicAdd(&g_den[d * HEADS + hh], ex);
}

// layernorm(relu(agg/den + bias) + h); zero accumulators for the next layer
__global__ void k_ln(const float* __restrict__ bias, const float* __restrict__ s,
                     const float* __restrict__ bb) {
    __shared__ float red[HD];
    int n = blockIdx.x, t = threadIdx.x;
    float den = g_den[n * HEADS + (t >> 5)];
    float v = g_agg[n * HD + t] / den + bias[t];
    g_agg[n * HD + t] = 0.f;
    if (t < HEADS) g_den[n * HEADS + t] = 0.f;
    v = v > 0.f ? v : 0.f;
    v += g_h[n * HD + t];
    red[t] = v; __syncthreads();
#pragma unroll
    for (int o = 64; o > 0; o >>= 1) { if (t < o) red[t] += red[t + o]; __syncthreads(); }
    float mu = red[0] / (float)HD;
    __syncthreads();
    float dd = v - mu;
    red[t] = dd * dd; __syncthreads();
#pragma unroll
    for (int o = 64; o > 0; o >>= 1) { if (t < o) red[t] += red[t + o]; __syncthreads(); }
    float var = red[0] / (float)HD;
    g_h[n * HD + t] = dd * rsqrtf(var + 1e-5f) * s[t] + bb[t];
    if (n == 0 && t < HEADS) g_aesum[t] = 0.f;
}

// onsite (nodes) + coupling (edges) MLPs: 128 -> 64 (relu) -> 1
__global__ void k_mlp(const float* __restrict__ w1, const float* __restrict__ b1,
                      const float* __restrict__ w2, const float* __restrict__ b2,
                      const float* __restrict__ cw1, const float* __restrict__ cb1,
                      const float* __restrict__ cw2, const float* __restrict__ cb2,
                      int N) {
    __shared__ float in[HD];
    __shared__ float red[64];
    int blk = blockIdx.x, t = threadIdx.x;
    const float *row, *W1, *B1, *W2, *B2;
    if (blk < N) { row = &g_h[blk * HD];        W1 = w1;  B1 = b1;  W2 = w2;  B2 = b2;  }
    else         { row = &g_e[(blk - N) * HD];  W1 = cw1; B1 = cb1; W2 = cw2; B2 = cb2; }
    in[t] = row[t]; in[t + 64] = row[t + 64];
    __syncthreads();
    float acc = B1[t];
#pragma unroll 8
    for (int k = 0; k < HD; k++) acc = fmaf(in[k], W1[k * 64 + t], acc);
    acc = acc > 0.f ? acc : 0.f;
    red[t] = acc * W2[t];
    __syncthreads();
#pragma unroll
    for (int o = 32; o > 0; o >>= 1) { if (t < o) red[t] += red[t + o]; __syncthreads(); }
    if (t == 0) {
        float o = red[0] + B2[0];
        if (blk < N) g_onsite[blk] = o; else g_coup[blk - N] = o;
    }
}

// dna mask + local dna-index per graph; also zero band arrays for k_basm
__global__ void k_dna(const float* __restrict__ x, const int* __restrict__ batch,
                      int N, int B) {
    __shared__ int mi[N_MAX];
    __shared__ int bt[N_MAX];
    __shared__ int lo[N_MAX];
    int t = threadIdx.x;
    for (int i = t; i < B * HS; i += blockDim.x) {
        g_hbd[i] = 0.f; g_hb1[i] = 0.f; g_hb2[i] = 0.f;
    }
    for (int n = t; n < N; n += blockDim.x) {
        float a = x[n * 4], b = x[n * 4 + 1], c = x[n * 4 + 2], d = x[n * 4 + 3];
        int dna = (a != 0.f || b != 0.f || c != 0.f || d != 0.f) ? 1 : 0;
        mi[n] = dna;
        g_dna[n] = dna;
        bt[n] = batch[n];
    }
    __syncthreads();
    if (t == 0) {
        int cum = 0, curb = -1, gstart = 0;
        for (int n = 0; n < N; n++) {
            int b = bt[n];
            if (b != curb) { curb = b; gstart = cum; }
            lo[n] = cum - gstart;
            cum += mi[n];
        }
    }
    __syncthreads();
    for (int n = t; n < N; n += blockDim.x) g_loc[n] = lo[n];
}

// assemble bands: onsite->diag, coup->band1/band2, dvb from GL/GR
__global__ void k_basm(const int* __restrict__ src, const int* __restrict__ dst,
                       const int* __restrict__ batch,
                       const float* __restrict__ GL, const float* __restrict__ GR,
                       int N, int E, int B) {
    int idx = blockIdx.x * blockDim.x + threadIdx.x;
    if (idx < N) {
        if (g_dna[idx])
            atomicAdd(&g_hbd[batch[idx] * HS + g_loc[idx]], g_onsite[idx]);
    } else if (idx < N + E) {
        int e = idx - N;
        int s = src[e], d = dst[e];
        if (g_dna[s] && g_dna[d]) {
            int b = batch[s], u = g_loc[s], v = g_loc[d];
            int lo = u < v ? u : v;
            int bd = u < v ? v - u : u - v;
            float cv = g_coup[e];
            if (bd == 1)      atomicAdd(&g_hb1[b * HS + lo], cv);
            else if (bd == 2) atomicAdd(&g_hb2[b * HS + lo], cv);
        }
    } else if (idx < N + E + B * HS) {
        int i = idx - N - E;
        g_dvb[i] = 0.5f * (GL[i] + GR[i]) + 1e-12f;
    }
}

// write dense H (output) from bands
__global__ void k_hwrite(float* __restrict__ H, int B) {
    int idx = blockIdx.x * blockDim.x + threadIdx.x;
    if (idx >= B * HS * HS) return;
    int b = idx / (HS * HS);
    int r = (idx % (HS * HS)) / HS, c = idx % HS;
    float v;
    int lo = r < c ? r : c;
    int bd = r < c ? c - r : r - c;
    if (bd == 0)      v = g_hbd[b * HS + r] + 1e-6f;
    else if (bd == 1) v = g_hb1[b * HS + lo];
    else if (bd == 2) v = g_hb2[b * HS + lo];
    else              v = 0.f;
    H[idx] = v;
}

// ---------------- NEGF: banded (pentadiagonal) solver ----------------------
// banded LU: one thread per (b,e); writes a,b,e,f,dinv bands to g_lu
__global__ void k_lu(int BE) {
    int be = blockIdx.x * blockDim.x + threadIdx.x;
    if (be >= BE) return;
    int b = be / NEG, e = be % NEG;
    float Eg = (float)(-3.0 + 6.0 * (double)e / 99.0);
    const float* hd = g_hbd + b * HS;
    const float* h1 = g_hb1 + b * HS;
    const float* h2 = g_hb2 + b * HS;
    const float* dv = g_dvb + b * HS;
    float2* out = g_lu + (size_t)be * 5 * HS;
    g_Tacc[be] = 0.f; g_Dacc[be] = 0.f; g_cnt[be] = 0;

    float2 e1 = {0.f, 0.f}, e2 = {0.f, 0.f};
    float2 f1 = {0.f, 0.f}, f2 = {0.f, 0.f};
    float2 di1 = {0.f, 0.f}, di2 = {0.f, 0.f};
    for (int i = 0; i < HS; i++) {
        float2 Mi = make_float2(Eg - (hd[i] + 1e-6f), dv[i]);
        float m1 = (i >= 1) ? -h1[i - 1] : 0.f;
        float m2 = (i >= 2) ? -h2[i - 2] : 0.f;
        float2 bi = make_float2(m2 * di2.x, m2 * di2.y);
        float2 tt = make_float2(m1, 0.f);
        CFMS(tt, bi, e2);                          // m1 - bi*e2
        float2 ai; CMUL(ai, tt, di1);              // / d_{i-1}
        float2 d = Mi;
        CFMS(d, bi, f2);
        CFMS(d, ai, e1);
        float2 ei = make_float2(0.f, 0.f);
        if (i < HS - 1) { ei = make_float2(-h1[i], 0.f); CFMS(ei, ai, f1); }
        float2 fi = make_float2((i < HS - 2) ? -h2[i] : 0.f, 0.f);
        float inv = 1.f / fmaf(d.x, d.x, d.y * d.y);
        float2 dinv = make_float2(d.x * inv, -d.y * inv);
        out[0 * HS + i] = ai;
        out[1 * HS + i] = bi;
        out[2 * HS + i] = ei;
        out[3 * HS + i] = fi;
        out[4 * HS + i] = dinv;
        e2 = e1; e1 = ei; f2 = f1; f1 = fi; di2 = di1; di1 = dinv;
    }
}

// column solves: one warp-CTA per (b,e, quarter); lane = column j.
// Last CTA per (b,e) also writes the final log10 outputs.
__global__ void __launch_bounds__(32) k_solve(
    const float* __restrict__ GL, const float* __restrict__ GR,
    float* __restrict__ Tout, float* __restrict__ Dout, int BE) {
    __shared__ float2 ys[HS * 32];       // 32KB: per-lane y history
    __shared__ float2 sa[HS], sb[HS], se[HS], sf[HS], sdi[HS];
    __shared__ float  sgl[HS], sgr[HS];
    int blk = blockIdx.x;
    int be = blk >> 2, q = blk & 3;
    int b = be / NEG;
    int lane = threadIdx.x;
    const float2* lu = g_lu + (size_t)be * 5 * HS;
#pragma unroll
    for (int k = 0; k < 4; k++) {
        int i = lane + k * 32;
        sa[i]  = lu[0 * HS + i];
        sb[i]  = lu[1 * HS + i];
        se[i]  = lu[2 * HS + i];
        sf[i]  = lu[3 * HS + i];
        sdi[i] = lu[4 * HS + i];
        sgl[i] = GL[b * HS + i];
        sgr[i] = GR[b * HS + i];
    }
    __syncwarp();

    int j = q * 32 + lane;
    int i0 = q * 32;
    // forward: L y = e_j (y_i = 0 for i < i0 <= j)
    float2 y1 = {0.f, 0.f}, y2 = {0.f, 0.f};
    for (int i = i0; i < HS; i++) {
        float2 y = make_float2((i == j) ? 1.f : 0.f, 0.f);
        CFMS(y, sa[i], y1);
        CFMS(y, sb[i], y2);
        ys[i * 32 + lane] = y;
        y2 = y1; y1 = y;
    }
    // backward: U x = y ; accumulate sum_i gl_i |x_i|^2 and Im x_jj
    float2 x1 = {0.f, 0.f}, x2 = {0.f, 0.f};
    float tp = 0.f, dj = 0.f;
    for (int i = HS - 1; i >= 0; i--) {
        float2 t = (i >= i0) ? ys[i * 32 + lane] : make_float2(0.f, 0.f);
        CFMS(t, se[i], x1);
        CFMS(t, sf[i], x2);
        float2 x; CMUL(x, t, sdi[i]);
        tp = fmaf(sgl[i], fmaf(x.x, x.x, x.y * x.y), tp);
        if (i == j) dj = x.y;
        x2 = x1; x1 = x;
    }
    tp *= sgr[j];
#pragma unroll
    for (int o = 16; o > 0; o >>= 1) {
        tp += __shfl_down_sync(0xffffffffu, tp, o);
        dj += __shfl_down_sync(0xffffffffu, dj, o);
    }
    if (lane == 0) {
        atomicAdd(&g_Tacc[be], tp);
        atomicAdd(&g_Dacc[be], dj);
        __threadfence();
        int old = atomicAdd(&g_cnt[be], 1);
        if (old == 3) {
            __threadfence();
            Tout[be] = log10f(fmaxf(g_Tacc[be], 1e-16f));
            Dout[be] = log10f(fmaxf(-g_Dacc[be] / 3.14159265358979323846f, 1e-16f));
        }
    }
}

// ---------------- launch ----------------------------------------------------
extern "C" void kernel_launch(void* const* d_in, const int* in_sizes, int n_in,
                              void* d_out, int out_size) {
    const float* x      = (const float*)d_in[0];
    const int*   ei     = (const int*)  d_in[1];
    const float* ea     = (const float*)d_in[2];
    const int*   batch  = (const int*)  d_in[3];
    const float* GL     = (const float*)d_in[4];
    const float* GR     = (const float*)d_in[5];
    const float* node_w = (const float*)d_in[6];
    const float* node_b = (const float*)d_in[7];
    const float* edgep_w= (const float*)d_in[8];
    const float* edgep_b= (const float*)d_in[9];
    const float* gat_lin= (const float*)d_in[10];
    const float* att_src= (const float*)d_in[11];
    const float* att_dst= (const float*)d_in[12];
    const float* gat_le = (const float*)d_in[13];
    const float* att_ed = (const float*)d_in[14];
    const float* gat_b  = (const float*)d_in[15];
    const float* ln_s   = (const float*)d_in[16];
    const float* ln_b   = (const float*)d_in[17];
    const float* on_w1  = (const float*)d_in[18];
    const float* on_b1  = (const float*)d_in[19];
    const float* on_w2  = (const float*)d_in[20];
    const float* on_b2  = (const float*)d_in[21];
    const float* cp_w1  = (const float*)d_in[22];
    const float* cp_b1  = (const float*)d_in[23];
    const float* cp_w2  = (const float*)d_in[24];
    const float* cp_b2  = (const float*)d_in[25];

    int N = in_sizes[0] / 4;
    int E = in_sizes[2] / 5;
    int B = in_sizes[4] / HS;
    int BE = B * NEG;
    const int* src = ei;
    const int* dst = ei + E;

    float* out  = (float*)d_out;
    float* Tout = out;
    float* Dout = out + BE;
    float* Hout = out + 2 * BE;

    k_init_h<<<N, HD>>>(x, node_w, node_b);
    k_init_e<<<E, HD>>>(ea, edgep_w, edgep_b);

    int nb_n = (N + 3) / 4, nb_e = (E + 3) / 4;
    for (int l = 0; l < NLAYER; l++) {
        k_attn   <<<nb_n + nb_e, HD>>>(gat_lin + l * HD * HD, att_src + l * HEADS * CDIM,
                                       att_dst + l * HEADS * CDIM, gat_le + l * HD * HD,
                                       att_ed + l * HEADS * CDIM, N, E, nb_n);
        k_edgeagg<<<E + N, HD>>>(src, dst, N, E);
        k_ln     <<<N, HD>>>(gat_b + l * HD, ln_s + l * HD, ln_b + l * HD);
    }

    k_mlp <<<N + E, 64>>>(on_w1, on_b1, on_w2, on_b2, cp_w1, cp_b1, cp_w2, cp_b2, N);
    k_dna <<<1, 1024>>>(x, batch, N, B);
    int tot = N + E + B * HS;
    k_basm<<<(tot + 255) / 256, 256>>>(src, dst, batch, GL, GR, N, E, B);
    k_hwrite<<<(B * HS * HS + 255) / 256, 256>>>(Hout, B);
    k_lu   <<<(BE + 127) / 128, 128>>>(BE);
    k_solve<<<BE * 4, 32>>>(GL, GR, Tout, Dout, BE);
}